// round 3
// baseline (speedup 1.0000x reference)
#include <cuda_runtime.h>

// ---------------- problem constants ----------------
#define DT_F 0.01f
constexpr int N    = 64;     // state dim
constexpr int RNK  = 4;      // low rank
constexpr int DIN  = 128;
constexpr int DOUT = 128;
constexpr int BATCH = 32;
constexpr int T    = 8192;
constexpr int L    = 128;            // chunk length
constexpr int G    = T / L;          // 64 chunks
constexpr int BT   = BATCH * T;      // 262144

// ---------------- device scratch (static, no allocs) ----------------
__device__ float2 g_bu[(size_t)BT * N];      // 128 MB : B_d @ u  (complex)
__device__ float  g_xr[(size_t)BT * N];      // 64 MB  : Re(x_t)
__device__ float2 g_Bd[DIN * N];             // B_d transposed: [i][n]
__device__ float2 g_Da[N];
__device__ float2 g_U[N * RNK];
__device__ float2 g_V[RNK * N];
__device__ float2 g_Ad[N * N];
__device__ float2 g_Atmp[N * N];
__device__ float2 g_csum[BATCH * G * N];
__device__ float2 g_xin[BATCH * G * N];
__device__ float  g_CT[N * DOUT];            // C transposed: [k][o]
__device__ float  g_DT[DIN * DOUT];          // D transposed: [k][o]
__device__ int    g_dflag;

// ---------------- helpers ----------------
__device__ __forceinline__ float2 cfma(float2 a, float2 b, float2 c) { // c + a*b
    float2 r;
    r.x = fmaf(a.x, b.x, fmaf(-a.y, b.y, c.x));
    r.y = fmaf(a.x, b.y, fmaf( a.y, b.x, c.y));
    return r;
}
__device__ __forceinline__ float2 cmulf(float2 a, float2 b) {
    return cfma(a, b, make_float2(0.f, 0.f));
}
__device__ __forceinline__ unsigned long long ffma2(unsigned long long a,
                                                    unsigned long long b,
                                                    unsigned long long c) {
    unsigned long long d;
    asm("fma.rn.f32x2 %0, %1, %2, %3;" : "=l"(d) : "l"(a), "l"(b), "l"(c));
    return d;
}
__device__ __forceinline__ unsigned long long pack2(float x, float y) {
    unsigned long long r;
    asm("mov.b64 %0, {%1, %2};" : "=l"(r) : "f"(x), "f"(y));
    return r;
}
__device__ __forceinline__ float2 unpack2(unsigned long long v) {
    float x, y;
    asm("mov.b64 {%0, %1}, %2;" : "=f"(x), "=f"(y) : "l"(v));
    return make_float2(x, y);
}

// ---------------- setup: Woodbury factors, B_d, dense A_d, transposes ----------------
__global__ void setup_kernel(const float* __restrict__ lw, const float* __restrict__ zl,
                             const float* __restrict__ P,  const float* __restrict__ Q,
                             const float* __restrict__ Bm, const float* __restrict__ C,
                             const float* __restrict__ D) {
    __shared__ float2 sminv[N];
    __shared__ float2 sS[16];
    __shared__ float2 sK[16];
    __shared__ float2 sW[RNK * DIN];
    const float c = 0.5f * DT_F;
    const int t = threadIdx.x;   // 128 threads

    if (t < N) {
        float om = expf(lw[t]);
        float ze = 1.f / (1.f + expf(-zl[t]));
        float lr = -ze * om;
        float li = om * sqrtf(fmaxf(1.f - ze * ze, 1e-8f));
        float mr = 1.f - c * lr;
        float mi = -c * li;
        float inv = 1.f / (mr * mr + mi * mi);
        sminv[t] = make_float2(mr * inv, -mi * inv);
    }
    __syncthreads();

    // S = c * Q^T Minv P  (4x4 complex)
    if (t < 16) {
        int r = t >> 2, s2 = t & 3;
        float2 acc = make_float2(0.f, 0.f);
        for (int k = 0; k < N; k++) {
            float coef = Q[k * RNK + r] * P[k * RNK + s2];
            acc.x += coef * sminv[k].x;
            acc.y += coef * sminv[k].y;
        }
        sS[t] = make_float2(c * acc.x, c * acc.y);
    }
    __syncthreads();

    // K = inv(I4 - S), Gauss-Jordan (well conditioned: S ~ 1e-4)
    if (t == 0) {
        float2 M_[4][8];
        for (int i = 0; i < 4; i++)
            for (int j = 0; j < 4; j++) {
                float2 v = sS[i * 4 + j];
                M_[i][j] = make_float2((i == j ? 1.f : 0.f) - v.x, -v.y);
                M_[i][4 + j] = make_float2(i == j ? 1.f : 0.f, 0.f);
            }
        for (int col = 0; col < 4; col++) {
            float2 p = M_[col][col];
            float d = 1.f / (p.x * p.x + p.y * p.y);
            float2 pinv = make_float2(p.x * d, -p.y * d);
            for (int j = 0; j < 8; j++) M_[col][j] = cmulf(M_[col][j], pinv);
            for (int rr = 0; rr < 4; rr++)
                if (rr != col) {
                    float2 f = M_[rr][col];
                    for (int j = 0; j < 8; j++) {
                        float2 s = cmulf(f, M_[col][j]);
                        M_[rr][j].x -= s.x;
                        M_[rr][j].y -= s.y;
                    }
                }
        }
        for (int i = 0; i < 4; i++)
            for (int j = 0; j < 4; j++) sK[i * 4 + j] = M_[i][4 + j];
    }
    __syncthreads();

    // Da, U, V
    if (t < N) {
        float2 mv = sminv[t];
        g_Da[t] = make_float2(2.f * mv.x - 1.f, 2.f * mv.y);
        #pragma unroll
        for (int r = 0; r < RNK; r++) {
            float2 pk = make_float2(0.f, 0.f);
            #pragma unroll
            for (int s2 = 0; s2 < RNK; s2++) {
                float pv = P[t * RNK + s2];
                pk.x += pv * sK[s2 * 4 + r].x;
                pk.y += pv * sK[s2 * 4 + r].y;
            }
            float2 u = cmulf(make_float2(2.f * c * mv.x, 2.f * c * mv.y), pk);
            g_U[t * RNK + r] = u;
            float qv = Q[t * RNK + r];
            g_V[r * N + t] = make_float2(qv * mv.x, qv * mv.y);
        }
    }
    __syncthreads();

    // W[r][i] = sum_k V[r][k] * B[k][i]
    {
        int i = t;  // 128 threads, i in [0,128)
        #pragma unroll
        for (int r = 0; r < RNK; r++) {
            float2 acc = make_float2(0.f, 0.f);
            for (int k = 0; k < N; k++) {
                float coef = Q[k * RNK + r] * Bm[k * DIN + i];
                acc.x += coef * sminv[k].x;
                acc.y += coef * sminv[k].y;
            }
            sW[r * DIN + i] = acc;
        }
    }
    __syncthreads();

    // B_d (transposed store): g_Bd[i*N + j] = sqrt(dt)*( minv_j*B[j][i] + 0.5*sum_r U[j][r]*W[r][i] )
    const float sq = sqrtf(DT_F);
    for (int idx = t; idx < N * DIN; idx += 128) {
        int j = idx >> 7, i = idx & 127;
        float2 mv = sminv[j];
        float bv = Bm[j * DIN + i];
        float2 acc = make_float2(bv * mv.x, bv * mv.y);
        #pragma unroll
        for (int r = 0; r < RNK; r++) {
            float2 u = g_U[j * RNK + r];
            acc = cfma(make_float2(0.5f * u.x, 0.5f * u.y), sW[r * DIN + i], acc);
        }
        g_Bd[i * N + j] = make_float2(sq * acc.x, sq * acc.y);
    }
    // dense A_d
    for (int idx = t; idx < N * N; idx += 128) {
        int j = idx >> 6, k = idx & 63;
        float2 acc = (j == k) ? g_Da[j] : make_float2(0.f, 0.f);
        #pragma unroll
        for (int r = 0; r < RNK; r++) acc = cfma(g_U[j * RNK + r], g_V[r * N + k], acc);
        g_Ad[j * N + k] = acc;
    }
    // transposes
    for (int idx = t; idx < DOUT * N; idx += 128) {
        int o = idx & 127, k = idx >> 7;
        g_CT[k * DOUT + o] = C[o * N + k];
    }
    for (int idx = t; idx < DOUT * DIN; idx += 128) {
        int o = idx & 127, k = idx >> 7;
        g_DT[k * DOUT + o] = D[o * DIN + k];
    }
}

// ---------------- A^2 repeated squaring (64x64 complex) ----------------
__global__ void sqmat_kernel(int srcSel) {
    const float2* src = srcSel ? g_Atmp : g_Ad;
    float2*       dst = srcSel ? g_Ad : g_Atmp;
    __shared__ float2 srow[N];
    int row = blockIdx.x, t = threadIdx.x;
    srow[t] = src[row * N + t];
    __syncthreads();
    float2 acc = make_float2(0.f, 0.f);
    for (int k = 0; k < N; k++) acc = cfma(srow[k], src[k * N + t], acc);
    dst[row * N + t] = acc;
}

// ---------------- bu = u @ B_d^T  (complex out), packed f32x2 GEMM ----------------
__global__ __launch_bounds__(256) void bu_gemm_kernel(const float* __restrict__ u) {
    __shared__ float  su[32][129];
    __shared__ float2 sb[32][66];
    const int tid = threadIdx.x;
    const int tx = tid & 15, ty = tid >> 4;
    const size_t bt0 = (size_t)blockIdx.x * 128;

    unsigned long long acc[8][4];
    #pragma unroll
    for (int i = 0; i < 8; i++)
        #pragma unroll
        for (int j = 0; j < 4; j++) acc[i][j] = 0ull;

    for (int k0 = 0; k0 < DIN; k0 += 32) {
        // u tile: 128 rows x 32 k
        #pragma unroll
        for (int l = 0; l < 4; l++) {
            int idx = tid + l * 256;         // float4 index, 0..1023
            int row = idx >> 3, k4 = idx & 7;
            float4 v = *(const float4*)&u[(bt0 + row) * DIN + k0 + k4 * 4];
            su[k4 * 4 + 0][row] = v.x;
            su[k4 * 4 + 1][row] = v.y;
            su[k4 * 4 + 2][row] = v.z;
            su[k4 * 4 + 3][row] = v.w;
        }
        // Bd tile: 32 k x 64 n (float2)
        #pragma unroll
        for (int l = 0; l < 4; l++) {
            int idx = tid + l * 256;         // float4 (=2 x float2) index
            int nn2 = idx & 31, kk = idx >> 5;
            float4 v = *(const float4*)&g_Bd[(k0 + kk) * N + nn2 * 2];
            *(float4*)&sb[kk][nn2 * 2] = v;
        }
        __syncthreads();
        #pragma unroll
        for (int k = 0; k < 32; k++) {
            unsigned long long a8[8], b4[4];
            #pragma unroll
            for (int i = 0; i < 8; i++) {
                float av = su[k][ty * 8 + i];
                a8[i] = pack2(av, av);
            }
            #pragma unroll
            for (int j = 0; j < 4; j++)
                b4[j] = *(const unsigned long long*)&sb[k][tx * 4 + j];
            #pragma unroll
            for (int i = 0; i < 8; i++)
                #pragma unroll
                for (int j = 0; j < 4; j++) acc[i][j] = ffma2(a8[i], b4[j], acc[i][j]);
        }
        __syncthreads();
    }
    #pragma unroll
    for (int i = 0; i < 8; i++) {
        #pragma unroll
        for (int jj = 0; jj < 2; jj++) {
            float2 lo = unpack2(acc[i][2 * jj]);
            float2 hi = unpack2(acc[i][2 * jj + 1]);
            float4 v = make_float4(lo.x, lo.y, hi.x, hi.y);
            *(float4*)&g_bu[(bt0 + ty * 8 + i) * N + tx * 4 + 2 * jj] = v;
        }
    }
}

// ---------------- chunked scan (mode 0: local sums from zero; mode 1: final pass) ----------------
__global__ __launch_bounds__(128) void scan_kernel(int mode) {
    const int w  = blockIdx.x * 4 + (threadIdx.x >> 5);   // 0..2047
    const int ln = threadIdx.x & 31;
    const int b = w >> 6;        // / G
    const int g = w & 63;        // % G
    const size_t bt0 = (size_t)b * T + (size_t)g * L;

    float2 da0 = g_Da[ln], da1 = g_Da[ln + 32];
    float2 U0[RNK], U1[RNK], V0[RNK], V1[RNK];
    #pragma unroll
    for (int r = 0; r < RNK; r++) {
        U0[r] = g_U[ln * RNK + r];
        U1[r] = g_U[(ln + 32) * RNK + r];
        V0[r] = g_V[r * N + ln];
        V1[r] = g_V[r * N + ln + 32];
    }
    float2 x0 = make_float2(0.f, 0.f), x1 = make_float2(0.f, 0.f);
    if (mode) {
        int ci = (b * G + g) * N;
        x0 = g_xin[ci + ln];
        x1 = g_xin[ci + ln + 32];
    }
    const float2* bup = g_bu + bt0 * N;
    float2 nb0 = bup[ln], nb1 = bup[ln + 32];

    for (int t = 0; t < L; t++) {
        float2 bu0 = nb0, bu1 = nb1;
        if (t + 1 < L) {
            nb0 = bup[(t + 1) * N + ln];
            nb1 = bup[(t + 1) * N + ln + 32];
        }
        float2 s[RNK];
        #pragma unroll
        for (int r = 0; r < RNK; r++) s[r] = cfma(V1[r], x1, cmulf(V0[r], x0));
        #pragma unroll
        for (int off = 16; off > 0; off >>= 1) {
            #pragma unroll
            for (int r = 0; r < RNK; r++) {
                s[r].x += __shfl_xor_sync(0xffffffffu, s[r].x, off);
                s[r].y += __shfl_xor_sync(0xffffffffu, s[r].y, off);
            }
        }
        float2 y0 = cfma(da0, x0, bu0);
        float2 y1 = cfma(da1, x1, bu1);
        #pragma unroll
        for (int r = 0; r < RNK; r++) {
            y0 = cfma(U0[r], s[r], y0);
            y1 = cfma(U1[r], s[r], y1);
        }
        x0 = y0;
        x1 = y1;
        if (mode) {
            g_xr[(bt0 + t) * N + ln]      = x0.x;
            g_xr[(bt0 + t) * N + ln + 32] = x1.x;
        }
    }
    if (!mode) {
        int ci = (b * G + g) * N;
        g_csum[ci + ln]      = x0;
        g_csum[ci + ln + 32] = x1;
    }
}

// ---------------- chunk-level chain: x_in[g+1] = A^L x_in[g] + c_g ----------------
__global__ __launch_bounds__(64) void chain_kernel() {
    __shared__ float2 sA[N * 65];
    __shared__ float2 sx[N];
    const int b = blockIdx.x, t = threadIdx.x;
    for (int i = t; i < N * N; i += 64) {
        int r = i >> 6, c = i & 63;
        sA[r * 65 + c] = g_Atmp[i];   // A^128 lives in g_Atmp after 7 squarings
    }
    float2 x = make_float2(0.f, 0.f);
    for (int g = 0; g < G; g++) {
        int ci = (b * G + g) * N;
        g_xin[ci + t] = x;
        sx[t] = x;
        __syncthreads();
        float2 acc = g_csum[ci + t];
        for (int k = 0; k < N; k++) acc = cfma(sA[t * 65 + k], sx[k], acc);
        x = acc;
        __syncthreads();
    }
}

// ---------------- D-zero flag ----------------
__global__ void dflag_kernel(const float* __restrict__ D) {
    __shared__ float red[256];
    int tid = threadIdx.x;
    float sum = 0.f;
    for (int i = tid; i < DOUT * DIN; i += 256) sum += fabsf(D[i]);
    red[tid] = sum;
    __syncthreads();
    for (int s = 128; s > 0; s >>= 1) {
        if (tid < s) red[tid] += red[tid + s];
        __syncthreads();
    }
    if (tid == 0) g_dflag = (red[0] != 0.f) ? 1 : 0;
}

// ---------------- y = Re(x) @ C^T (+ u @ D^T if D != 0), packed f32x2 GEMM ----------------
__global__ __launch_bounds__(256) void y_gemm_kernel(const float* __restrict__ u,
                                                     float* __restrict__ out) {
    __shared__ float sx[32][129];
    __shared__ float sc[32][132];
    const int tid = threadIdx.x;
    const int tx = tid & 15, ty = tid >> 4;
    const size_t bt0 = (size_t)blockIdx.x * 128;

    unsigned long long acc[8][4];
    #pragma unroll
    for (int i = 0; i < 8; i++)
        #pragma unroll
        for (int j = 0; j < 4; j++) acc[i][j] = 0ull;

    // main part: K = 64 over (xr, C^T)
    for (int k0 = 0; k0 < N; k0 += 32) {
        #pragma unroll
        for (int l = 0; l < 4; l++) {
            int idx = tid + l * 256;
            int row = idx >> 3, k4 = idx & 7;
            float4 v = *(const float4*)&g_xr[(bt0 + row) * N + k0 + k4 * 4];
            sx[k4 * 4 + 0][row] = v.x;
            sx[k4 * 4 + 1][row] = v.y;
            sx[k4 * 4 + 2][row] = v.z;
            sx[k4 * 4 + 3][row] = v.w;
        }
        #pragma unroll
        for (int l = 0; l < 4; l++) {
            int idx = tid + l * 256;
            int o4 = idx & 31, kk = idx >> 5;
            float4 v = *(const float4*)&g_CT[(k0 + kk) * DOUT + o4 * 4];
            *(float4*)&sc[kk][o4 * 4] = v;
        }
        __syncthreads();
        #pragma unroll
        for (int k = 0; k < 32; k++) {
            unsigned long long a8[8], b4[4];
            #pragma unroll
            for (int i = 0; i < 8; i++) {
                float av = sx[k][ty * 8 + i];
                a8[i] = pack2(av, av);
            }
            #pragma unroll
            for (int j = 0; j < 4; j++)
                b4[j] = *(const unsigned long long*)&sc[k][tx * 8 + 2 * j];
            #pragma unroll
            for (int i = 0; i < 8; i++)
                #pragma unroll
                for (int j = 0; j < 4; j++) acc[i][j] = ffma2(a8[i], b4[j], acc[i][j]);
        }
        __syncthreads();
    }
    // feedthrough: only when D is nonzero (it is all-zeros in this dataset)
    if (g_dflag) {
        for (int k0 = 0; k0 < DIN; k0 += 32) {
            #pragma unroll
            for (int l = 0; l < 4; l++) {
                int idx = tid + l * 256;
                int row = idx >> 3, k4 = idx & 7;
                float4 v = *(const float4*)&u[(bt0 + row) * DIN + k0 + k4 * 4];
                sx[k4 * 4 + 0][row] = v.x;
                sx[k4 * 4 + 1][row] = v.y;
                sx[k4 * 4 + 2][row] = v.z;
                sx[k4 * 4 + 3][row] = v.w;
            }
            #pragma unroll
            for (int l = 0; l < 4; l++) {
                int idx = tid + l * 256;
                int o4 = idx & 31, kk = idx >> 5;
                float4 v = *(const float4*)&g_DT[(k0 + kk) * DOUT + o4 * 4];
                *(float4*)&sc[kk][o4 * 4] = v;
            }
            __syncthreads();
            #pragma unroll
            for (int k = 0; k < 32; k++) {
                unsigned long long a8[8], b4[4];
                #pragma unroll
                for (int i = 0; i < 8; i++) {
                    float av = sx[k][ty * 8 + i];
                    a8[i] = pack2(av, av);
                }
                #pragma unroll
                for (int j = 0; j < 4; j++)
                    b4[j] = *(const unsigned long long*)&sc[k][tx * 8 + 2 * j];
                #pragma unroll
                for (int i = 0; i < 8; i++)
                    #pragma unroll
                    for (int j = 0; j < 4; j++) acc[i][j] = ffma2(a8[i], b4[j], acc[i][j]);
            }
            __syncthreads();
        }
    }
    #pragma unroll
    for (int i = 0; i < 8; i++) {
        float2 p0 = unpack2(acc[i][0]);
        float2 p1 = unpack2(acc[i][1]);
        float2 p2 = unpack2(acc[i][2]);
        float2 p3 = unpack2(acc[i][3]);
        float4 v0 = make_float4(p0.x, p0.y, p1.x, p1.y);
        float4 v1 = make_float4(p2.x, p2.y, p3.x, p3.y);
        size_t base = (bt0 + ty * 8 + i) * DOUT + tx * 8;
        *(float4*)&out[base]     = v0;
        *(float4*)&out[base + 4] = v1;
    }
}

// ---------------- launch ----------------
extern "C" void kernel_launch(void* const* d_in, const int* in_sizes, int n_in,
                              void* d_out, int out_size) {
    const float* u  = (const float*)d_in[0];
    const float* lw = (const float*)d_in[1];
    const float* zl = (const float*)d_in[2];
    const float* P  = (const float*)d_in[3];
    const float* Q  = (const float*)d_in[4];
    const float* Bm = (const float*)d_in[5];
    const float* C  = (const float*)d_in[6];
    const float* D  = (const float*)d_in[7];
    float* out = (float*)d_out;

    setup_kernel<<<1, 128>>>(lw, zl, P, Q, Bm, C, D);
    for (int i = 0; i < 7; i++) sqmat_kernel<<<N, N>>>(i & 1);  // A_d^128 -> g_Atmp
    bu_gemm_kernel<<<BT / 128, 256>>>(u);
    scan_kernel<<<(BATCH * G) / 4, 128>>>(0);   // local chunk sums
    chain_kernel<<<BATCH, 64>>>();              // chunk-level recurrence
    scan_kernel<<<(BATCH * G) / 4, 128>>>(1);   // final pass, store Re(x)
    dflag_kernel<<<1, 256>>>(D);
    y_gemm_kernel<<<BT / 128, 256>>>(u, out);
}